// round 13
// baseline (speedup 1.0000x reference)
#include <cuda_runtime.h>
#include <cuda_fp16.h>
#include <cstdint>
#include <math.h>

#define SQ   2048
#define DIM  768
#define NH   12
#define HD   64
#define QKVD 2304
#define FFD  384
#define MAXN 128

// ---------------- scratch (device globals; no allocation allowed) ----------------
__device__ float g_xin[SQ * DIM];     // LN0 output fp32 (for residual)
__device__ float g_prj[SQ * DIM];
__device__ float g_x1 [SQ * DIM];     // LN1 output fp32 (for residual)
__device__ float g_ff [SQ * DIM];
__device__ __half g_qkv_h[SQ * QKVD]; // qkv in fp16 (only attn reads it)
__device__ __half g_xin_h[SQ * DIM];  // fp16 GEMM operands
__device__ __half g_att_h[SQ * DIM];
__device__ __half g_x1_h [SQ * DIM];
__device__ __half g_hh_h [SQ * FFD];
__device__ __half g_wq [QKVD * DIM];
__device__ __half g_wo [DIM * DIM];
__device__ __half g_w1 [FFD * DIM];
__device__ __half g_w2 [DIM * FFD];
__device__ int   g_nbr[SQ * MAXN];
__device__ int   g_cnt[SQ];

// ---------------- PTX helpers (sm_80-era only) ----------------
__device__ __forceinline__ uint32_t smem_u32(const void* p) {
    uint32_t a;
    asm("{ .reg .u64 t; cvta.to.shared.u64 t, %1; cvt.u32.u64 %0, t; }" : "=r"(a) : "l"(p));
    return a;
}
#define CP_ASYNC16(dst, src) \
    asm volatile("cp.async.cg.shared.global [%0], [%1], 16;" :: "r"(dst), "l"(src))
#define CP_COMMIT() asm volatile("cp.async.commit_group;" ::: "memory")
#define CP_WAIT(n)  asm volatile("cp.async.wait_group %0;" :: "n"(n) : "memory")

__device__ __forceinline__ void ldsm_x4(uint32_t (&r)[4], uint32_t addr) {
    asm volatile("ldmatrix.sync.aligned.m8n8.x4.shared.b16 {%0,%1,%2,%3}, [%4];"
                 : "=r"(r[0]), "=r"(r[1]), "=r"(r[2]), "=r"(r[3]) : "r"(addr));
}
__device__ __forceinline__ void ldsm_x2(uint32_t (&r)[2], uint32_t addr) {
    asm volatile("ldmatrix.sync.aligned.m8n8.x2.shared.b16 {%0,%1}, [%2];"
                 : "=r"(r[0]), "=r"(r[1]) : "r"(addr));
}
__device__ __forceinline__ void mma_f16(float (&d)[4], const uint32_t (&a)[4],
                                        const uint32_t (&b)[2]) {
    asm volatile("mma.sync.aligned.m16n8k16.row.col.f32.f16.f16.f32 "
                 "{%0,%1,%2,%3}, {%4,%5,%6,%7}, {%8,%9}, {%0,%1,%2,%3};"
                 : "+f"(d[0]), "+f"(d[1]), "+f"(d[2]), "+f"(d[3])
                 : "r"(a[0]), "r"(a[1]), "r"(a[2]), "r"(a[3]), "r"(b[0]), "r"(b[1]));
}

// fp16 4-term dot: k (2x half2) . q (2x half2) -> float
__device__ __forceinline__ float dot4h(uint2 k, __half2 qa, __half2 qb) {
    __half2 d = __hmul2(*(const __half2*)&k.x, qa);
    d = __hfma2(*(const __half2*)&k.y, qb, d);
    float2 f = __half22float2(d);
    return f.x + f.y;
}

// ---------------- block reduce ----------------
__device__ __forceinline__ float block_sum(float v, float* sh) {
    #pragma unroll
    for (int o = 16; o > 0; o >>= 1) v += __shfl_down_sync(0xffffffffu, v, o);
    if ((threadIdx.x & 31) == 0) sh[threadIdx.x >> 5] = v;
    __syncthreads();
    if (threadIdx.x < 32) {
        float t = (threadIdx.x < 8) ? sh[threadIdx.x] : 0.f;
        #pragma unroll
        for (int o = 4; o > 0; o >>= 1) t += __shfl_down_sync(0xffffffffu, t, o);
        if (threadIdx.x == 0) sh[0] = t;
    }
    __syncthreads();
    float r = sh[0];
    __syncthreads();
    return r;
}

// ---------------- fused (a+b) -> LayerNorm (+ optional fp16 copy) ----------------
__global__ void add_ln_kernel(const float* __restrict__ a, const float* __restrict__ b,
                              const float* __restrict__ g, const float* __restrict__ be,
                              float* __restrict__ out, __half* __restrict__ outh) {
    __shared__ float sh[8];
    int row = blockIdx.x;
    const float* pa = a + (size_t)row * DIM;
    const float* pb = b + (size_t)row * DIM;
    float v[3]; float s = 0.f;
    #pragma unroll
    for (int i = 0; i < 3; i++) { int c = threadIdx.x + i * 256; v[i] = pa[c] + pb[c]; s += v[i]; }
    float mu = block_sum(s, sh) * (1.f / DIM);
    float s2 = 0.f;
    #pragma unroll
    for (int i = 0; i < 3; i++) { float d = v[i] - mu; s2 += d * d; }
    float var = block_sum(s2, sh) * (1.f / DIM);
    float rstd = rsqrtf(var + 1e-5f);
    #pragma unroll
    for (int i = 0; i < 3; i++) {
        int c = threadIdx.x + i * 256;
        float y = (v[i] - mu) * rstd * g[c] + be[c];
        out[(size_t)row * DIM + c] = y;
        if (outh) outh[(size_t)row * DIM + c] = __float2half_rn(y);
    }
}

// ---------------- prep: weight fp16 convert (y<4) + neighbor lists (y==4) --------
__global__ void prep_kernel(const int* __restrict__ adj,
                            const float* __restrict__ s0, __half* d0, int n0,
                            const float* __restrict__ s1, __half* d1, int n1,
                            const float* __restrict__ s2, __half* d2, int n2,
                            const float* __restrict__ s3, __half* d3, int n3) {
    if (blockIdx.y == 4) {
        int q = blockIdx.x;
        __shared__ int cnt;
        if (threadIdx.x == 0) cnt = 0;
        __syncthreads();
        const int4* row = (const int4*)(adj + (size_t)q * SQ);
        for (int c = threadIdx.x; c < SQ / 4; c += blockDim.x) {
            int4 v = row[c];
            int base = c * 4;
            if (v.x) { int p = atomicAdd(&cnt, 1); if (p < MAXN) g_nbr[q * MAXN + p] = base; }
            if (v.y) { int p = atomicAdd(&cnt, 1); if (p < MAXN) g_nbr[q * MAXN + p] = base + 1; }
            if (v.z) { int p = atomicAdd(&cnt, 1); if (p < MAXN) g_nbr[q * MAXN + p] = base + 2; }
            if (v.w) { int p = atomicAdd(&cnt, 1); if (p < MAXN) g_nbr[q * MAXN + p] = base + 3; }
        }
        __syncthreads();
        if (threadIdx.x == 0) g_cnt[q] = cnt < MAXN ? cnt : MAXN;
        return;
    }
    const float* x; __half* d; int n4;
    switch (blockIdx.y) {
        case 0: x = s0; d = d0; n4 = n0; break;
        case 1: x = s1; d = d1; n4 = n1; break;
        case 2: x = s2; d = d2; n4 = n2; break;
        default: x = s3; d = d3; n4 = n3; break;
    }
    int i = blockIdx.x * 256 + threadIdx.x;
    if (i < n4) {
        float4 v = ((const float4*)x)[i];
        __half2* p = (__half2*)(d + (size_t)i * 4);
        p[0] = __half2(__float2half_rn(v.x), __float2half_rn(v.y));
        p[1] = __half2(__float2half_rn(v.z), __float2half_rn(v.w));
    }
}

// ---------------- sparse attention: fp16 math, precomputed offsets ----------------
__global__ void attn_kernel() {
    int q    = blockIdx.x;
    int tid  = threadIdx.x;          // 192 threads
    int head = tid >> 4;             // 0..11
    int l    = tid & 15;             // 0..15 (4 dims each)
    __shared__ __half2 qv2[DIM / 2];
    __shared__ float sc[NH][MAXN];
    __shared__ int   noff[MAXN];     // precomputed element offsets (nbr * QKVD)

    int n = g_cnt[q];
    {
        const __half2* qrow = (const __half2*)(g_qkv_h + (size_t)q * QKVD);
        for (int i = tid; i < DIM / 2; i += 192) qv2[i] = qrow[i];
        for (int i = tid; i < n; i += 192) noff[i] = g_nbr[q * MAXN + i] * QKVD;
    }
    __syncthreads();

    const __half2 qa = qv2[(head * HD + l * 4) >> 1];
    const __half2 qb = qv2[(head * HD + l * 4) >> 1 | 1];
    const int koff = DIM + head * HD + l * 4;

    // score phase: 4 independent dot+reduce chains per round
    int j = 0;
    for (; j + 3 < n; j += 4) {
        const uint2 k0 = *(const uint2*)(g_qkv_h + (size_t)(noff[j]     + koff));
        const uint2 k1 = *(const uint2*)(g_qkv_h + (size_t)(noff[j + 1] + koff));
        const uint2 k2 = *(const uint2*)(g_qkv_h + (size_t)(noff[j + 2] + koff));
        const uint2 k3 = *(const uint2*)(g_qkv_h + (size_t)(noff[j + 3] + koff));
        float s0 = dot4h(k0, qa, qb);
        float s1 = dot4h(k1, qa, qb);
        float s2 = dot4h(k2, qa, qb);
        float s3 = dot4h(k3, qa, qb);
        #pragma unroll
        for (int o = 8; o > 0; o >>= 1) {
            s0 += __shfl_down_sync(0xffffffffu, s0, o, 16);
            s1 += __shfl_down_sync(0xffffffffu, s1, o, 16);
            s2 += __shfl_down_sync(0xffffffffu, s2, o, 16);
            s3 += __shfl_down_sync(0xffffffffu, s3, o, 16);
        }
        if (l == 0) {
            sc[head][j]     = s0 * 0.125f;
            sc[head][j + 1] = s1 * 0.125f;
            sc[head][j + 2] = s2 * 0.125f;
            sc[head][j + 3] = s3 * 0.125f;
        }
    }
    for (; j < n; j++) {
        const uint2 k0 = *(const uint2*)(g_qkv_h + (size_t)(noff[j] + koff));
        float s0 = dot4h(k0, qa, qb);
        #pragma unroll
        for (int o = 8; o > 0; o >>= 1) s0 += __shfl_down_sync(0xffffffffu, s0, o, 16);
        if (l == 0) sc[head][j] = s0 * 0.125f;
    }
    __syncwarp();

    // softmax over neighbors (per head, 16 lanes)
    float m = -INFINITY;
    for (int i = l; i < n; i += 16) m = fmaxf(m, sc[head][i]);
    #pragma unroll
    for (int o = 8; o > 0; o >>= 1) m = fmaxf(m, __shfl_xor_sync(0xffffffffu, m, o, 16));
    float sum = 0.f;
    for (int i = l; i < n; i += 16) { float e = __expf(sc[head][i] - m); sc[head][i] = e; sum += e; }
    #pragma unroll
    for (int o = 8; o > 0; o >>= 1) sum += __shfl_xor_sync(0xffffffffu, sum, o, 16);
    float inv = 1.f / sum;
    __syncwarp();

    // V accumulation, fp32, unroll 4
    const int voff = 2 * DIM + head * HD + l * 4;
    float4 A0 = make_float4(0.f, 0.f, 0.f, 0.f);
    float4 A1 = make_float4(0.f, 0.f, 0.f, 0.f);
    float4 A2 = make_float4(0.f, 0.f, 0.f, 0.f);
    float4 A3 = make_float4(0.f, 0.f, 0.f, 0.f);
    j = 0;
    for (; j + 3 < n; j += 4) {
        float p0 = sc[head][j] * inv,     p1 = sc[head][j + 1] * inv;
        float p2 = sc[head][j + 2] * inv, p3 = sc[head][j + 3] * inv;
        const uint2 v0 = *(const uint2*)(g_qkv_h + (size_t)(noff[j]     + voff));
        const uint2 v1 = *(const uint2*)(g_qkv_h + (size_t)(noff[j + 1] + voff));
        const uint2 v2 = *(const uint2*)(g_qkv_h + (size_t)(noff[j + 2] + voff));
        const uint2 v3 = *(const uint2*)(g_qkv_h + (size_t)(noff[j + 3] + voff));
        float2 a0 = __half22float2(*(const __half2*)&v0.x), a1 = __half22float2(*(const __half2*)&v0.y);
        float2 b0 = __half22float2(*(const __half2*)&v1.x), b1 = __half22float2(*(const __half2*)&v1.y);
        float2 c0 = __half22float2(*(const __half2*)&v2.x), c1 = __half22float2(*(const __half2*)&v2.y);
        float2 e0 = __half22float2(*(const __half2*)&v3.x), e1 = __half22float2(*(const __half2*)&v3.y);
        A0.x += p0 * a0.x; A0.y += p0 * a0.y; A0.z += p0 * a1.x; A0.w += p0 * a1.y;
        A1.x += p1 * b0.x; A1.y += p1 * b0.y; A1.z += p1 * b1.x; A1.w += p1 * b1.y;
        A2.x += p2 * c0.x; A2.y += p2 * c0.y; A2.z += p2 * c1.x; A2.w += p2 * c1.y;
        A3.x += p3 * e0.x; A3.y += p3 * e0.y; A3.z += p3 * e1.x; A3.w += p3 * e1.y;
    }
    for (; j < n; j++) {
        float p0 = sc[head][j] * inv;
        const uint2 v0 = *(const uint2*)(g_qkv_h + (size_t)(noff[j] + voff));
        float2 a0 = __half22float2(*(const __half2*)&v0.x), a1 = __half22float2(*(const __half2*)&v0.y);
        A0.x += p0 * a0.x; A0.y += p0 * a0.y; A0.z += p0 * a1.x; A0.w += p0 * a1.y;
    }
    float rx = A0.x + A1.x + A2.x + A3.x;
    float ry = A0.y + A1.y + A2.y + A3.y;
    float rz = A0.z + A1.z + A2.z + A3.z;
    float rw = A0.w + A1.w + A2.w + A3.w;

    __half2* ph = (__half2*)(g_att_h + (size_t)q * DIM + head * HD + l * 4);
    ph[0] = __half2(__float2half_rn(rx), __float2half_rn(ry));
    ph[1] = __half2(__float2half_rn(rz), __float2half_rn(rw));
}

// ---------------- fp16 GEMM 128x128, 256 threads (2x4 warps of 64x32) -----------
#define RSB      80
#define MATB     (128 * RSB)              // 10240
#define STAGEB   (2 * MATB)               // 20480 (A + B)
#define NSTAGE   3
#define GEMM_SMEM (NSTAGE * STAGEB)       // 61440 -> 2 CTAs/SM

__global__ void __launch_bounds__(256, 2)
gemm_h128(const __half* __restrict__ A, const __half* __restrict__ B,
          const float* __restrict__ bias, __half* __restrict__ Ch, int N, int K) {
    extern __shared__ char dsm[];
    const uint32_t sb = smem_u32(dsm);

    const int tid = threadIdx.x, wid = tid >> 5, lane = tid & 31;
    const int bm = blockIdx.y, bn = blockIdx.x;
    const int m0 = (wid >> 2) * 64, n0 = (wid & 3) * 32;

    const __half* Ag0 = A + (size_t)(bm * 128) * K;
    const __half* Bg0 = B + (size_t)(bn * 128) * K;

    const int lr = tid >> 2, lc = tid & 3;

    float acc[4][4][4];
    #pragma unroll
    for (int i = 0; i < 4; i++)
        #pragma unroll
        for (int j = 0; j < 4; j++)
            #pragma unroll
            for (int v = 0; v < 4; v++) acc[i][j][v] = 0.f;

    const int KT = K >> 5;

    auto load_stage = [&](int s, int kt) {
        uint32_t base = sb + s * STAGEB;
        const __half* Ag = Ag0 + kt * 32;
        const __half* Bg = Bg0 + kt * 32;
        #pragma unroll
        for (int j = 0; j < 2; j++) {
            int r = lr + j * 64;
            CP_ASYNC16(base +        r * RSB + lc * 16, Ag + (size_t)r * K + lc * 8);
            CP_ASYNC16(base + MATB + r * RSB + lc * 16, Bg + (size_t)r * K + lc * 8);
        }
        CP_COMMIT();
    };

    load_stage(0, 0);
    if (KT > 1) load_stage(1, 1); else CP_COMMIT();

    const int arow = lane & 15, ahalf = lane >> 4;
    const int brow = lane & 7,  bhalf = (lane >> 3) & 1;

    int stage = 0;
    for (int kt = 0; kt < KT; kt++) {
        CP_WAIT(1);
        __syncthreads();
        if (kt + 2 < KT) {
            int s = stage + 2; if (s >= NSTAGE) s -= NSTAGE;
            load_stage(s, kt + 2);
        } else CP_COMMIT();

        uint32_t base = sb + stage * STAGEB;
        #pragma unroll
        for (int ks = 0; ks < 2; ks++) {
            uint32_t af[4][4], bf[4][2];
            #pragma unroll
            for (int im = 0; im < 4; im++)
                ldsm_x4(af[im], base + (m0 + im * 16 + arow) * RSB + ks * 32 + ahalf * 16);
            #pragma unroll
            for (int in = 0; in < 4; in++)
                ldsm_x2(bf[in], base + MATB + (n0 + in * 8 + brow) * RSB + ks * 32 + bhalf * 16);
            #pragma unroll
            for (int im = 0; im < 4; im++)
                #pragma unroll
                for (int in = 0; in < 4; in++)
                    mma_f16(acc[im][in], af[im], bf[in]);
        }
        if (++stage == NSTAGE) stage = 0;
    }

    const int crow = lane >> 2, ccol = (lane & 3) * 2;
    #pragma unroll
    for (int im = 0; im < 4; im++) {
        #pragma unroll
        for (int in = 0; in < 4; in++) {
            int col = bn * 128 + n0 + in * 8 + ccol;
            float b0 = bias[col], b1 = bias[col + 1];
            #pragma unroll
            for (int half = 0; half < 2; half++) {
                int row = bm * 128 + m0 + im * 16 + crow + half * 8;
                float v0 = acc[im][in][half * 2 + 0] + b0;
                float v1 = acc[im][in][half * 2 + 1] + b1;
                *(__half2*)(Ch + (size_t)row * N + col) =
                    __half2(__float2half_rn(v0), __float2half_rn(v1));
            }
        }
    }
}

// ---------------- 64x64 fp16 variant (128 threads, 2x2 warps of 32x32) ----------
#define MATB64    (64 * RSB)              // 5120
#define STAGEB64  (2 * MATB64)            // 10240
#define GEMM_SMEM64 (NSTAGE * STAGEB64)   // 30720 -> 4 CTAs/SM

template <bool RELU, bool HOUT>
__global__ void __launch_bounds__(128, 4)
gemm_h64(const __half* __restrict__ A, const __half* __restrict__ B,
         const float* __restrict__ bias, float* __restrict__ C, __half* __restrict__ Ch,
         int N, int K) {
    extern __shared__ char dsm[];
    const uint32_t sb = smem_u32(dsm);

    const int tid = threadIdx.x, wid = tid >> 5, lane = tid & 31;
    const int bm = blockIdx.y, bn = blockIdx.x;
    const int m0 = (wid >> 1) * 32, n0 = (wid & 1) * 32;

    const __half* Ag0 = A + (size_t)(bm * 64) * K;
    const __half* Bg0 = B + (size_t)(bn * 64) * K;

    const int lr = tid >> 2, lc = tid & 3;

    float acc[2][4][4];
    #pragma unroll
    for (int i = 0; i < 2; i++)
        #pragma unroll
        for (int j = 0; j < 4; j++)
            #pragma unroll
            for (int v = 0; v < 4; v++) acc[i][j][v] = 0.f;

    const int KT = K >> 5;

    auto load_stage = [&](int s, int kt) {
        uint32_t base = sb + s * STAGEB64;
        const __half* Ag = Ag0 + kt * 32;
        const __half* Bg = Bg0 + kt * 32;
        #pragma unroll
        for (int j = 0; j < 2; j++) {
            int r = lr + j * 32;
            CP_ASYNC16(base +          r * RSB + lc * 16, Ag + (size_t)r * K + lc * 8);
            CP_ASYNC16(base + MATB64 + r * RSB + lc * 16, Bg + (size_t)r * K + lc * 8);
        }
        CP_COMMIT();
    };

    load_stage(0, 0);
    if (KT > 1) load_stage(1, 1); else CP_COMMIT();

    const int arow = lane & 15, ahalf = lane >> 4;
    const int brow = lane & 7,  bhalf = (lane >> 3) & 1;

    int stage = 0;
    for (int kt = 0; kt < KT; kt++) {
        CP_WAIT(1);
        __syncthreads();
        if (kt + 2 < KT) {
            int s = stage + 2; if (s >= NSTAGE) s -= NSTAGE;
            load_stage(s, kt + 2);
        } else CP_COMMIT();

        uint32_t base = sb + stage * STAGEB64;
        #pragma unroll
        for (int ks = 0; ks < 2; ks++) {
            uint32_t af[2][4], bf[4][2];
            #pragma unroll
            for (int im = 0; im < 2; im++)
                ldsm_x4(af[im], base + (m0 + im * 16 + arow) * RSB + ks * 32 + ahalf * 16);
            #pragma unroll
            for (int in = 0; in < 4; in++)
                ldsm_x2(bf[in], base + MATB64 + (n0 + in * 8 + brow) * RSB + ks * 32 + bhalf * 16);
            #pragma unroll
            for (int im = 0; im < 2; im++)
                #pragma unroll
                for (int in = 0; in < 4; in++)
                    mma_f16(acc[im][in], af[im], bf[in]);
        }
        if (++stage == NSTAGE) stage = 0;
    }

    const int crow = lane >> 2, ccol = (lane & 3) * 2;
    #pragma unroll
    for (int im = 0; im < 2; im++) {
        #pragma unroll
        for (int in = 0; in < 4; in++) {
            int col = bn * 64 + n0 + in * 8 + ccol;
            float b0 = bias[col], b1 = bias[col + 1];
            #pragma unroll
            for (int half = 0; half < 2; half++) {
                int row = bm * 64 + m0 + im * 16 + crow + half * 8;
                float v0 = acc[im][in][half * 2 + 0] + b0;
                float v1 = acc[im][in][half * 2 + 1] + b1;
                if (RELU) { v0 = fmaxf(v0, 0.f); v1 = fmaxf(v1, 0.f); }
                if (HOUT) {
                    *(__half2*)(Ch + (size_t)row * N + col) =
                        __half2(__float2half_rn(v0), __float2half_rn(v1));
                } else {
                    *(float2*)(C + (size_t)row * N + col) = make_float2(v0, v1);
                }
            }
        }
    }
}

// ---------------- launch ----------------
extern "C" void kernel_launch(void* const* d_in, const int* in_sizes, int n_in,
                              void* d_out, int out_size) {
    const float* exp_e = (const float*)d_in[0];
    const float* per_e = (const float*)d_in[1];
    const float* ipw   = (const float*)d_in[2];
    const float* ipb   = (const float*)d_in[3];
    const float* opw   = (const float*)d_in[4];
    const float* opb   = (const float*)d_in[5];
    const float* ln0g  = (const float*)d_in[6];
    const float* ln0b  = (const float*)d_in[7];
    const float* ln1g  = (const float*)d_in[8];
    const float* ln1b  = (const float*)d_in[9];
    const float* ln2g  = (const float*)d_in[10];
    const float* ln2b  = (const float*)d_in[11];
    const float* w1    = (const float*)d_in[12];
    const float* b1    = (const float*)d_in[13];
    const float* w2    = (const float*)d_in[14];
    const float* b2    = (const float*)d_in[15];
    const int*   adj   = (const int*)d_in[16];
    float* out = (float*)d_out;

    float *xin, *prj, *x1, *ff;
    __half *qkvh, *xinh, *atth, *x1h, *hhh, *wq, *wo, *wr1, *wr2;
    cudaGetSymbolAddress((void**)&xin, g_xin);
    cudaGetSymbolAddress((void**)&prj, g_prj);
    cudaGetSymbolAddress((void**)&x1,  g_x1);
    cudaGetSymbolAddress((void**)&ff,  g_ff);
    cudaGetSymbolAddress((void**)&qkvh, g_qkv_h);
    cudaGetSymbolAddress((void**)&xinh, g_xin_h);
    cudaGetSymbolAddress((void**)&atth, g_att_h);
    cudaGetSymbolAddress((void**)&x1h,  g_x1_h);
    cudaGetSymbolAddress((void**)&hhh,  g_hh_h);
    cudaGetSymbolAddress((void**)&wq,  g_wq);
    cudaGetSymbolAddress((void**)&wo,  g_wo);
    cudaGetSymbolAddress((void**)&wr1, g_w1);
    cudaGetSymbolAddress((void**)&wr2, g_w2);

    cudaFuncSetAttribute(gemm_h128, cudaFuncAttributeMaxDynamicSharedMemorySize, GEMM_SMEM);
    cudaFuncSetAttribute(gemm_h64<false, false>, cudaFuncAttributeMaxDynamicSharedMemorySize, GEMM_SMEM64);
    cudaFuncSetAttribute(gemm_h64<true,  true >, cudaFuncAttributeMaxDynamicSharedMemorySize, GEMM_SMEM64);

    // weights -> fp16 + neighbor lists, one launch
    prep_kernel<<<dim3(SQ, 5), 256>>>(adj,
        ipw, wq,  QKVD * DIM / 4,
        opw, wo,  DIM * DIM / 4,
        w1,  wr1, FFD * DIM / 4,
        w2,  wr2, DIM * FFD / 4);
    // x_in = LN0(exp + pert), fp32 + fp16
    add_ln_kernel<<<SQ, 256>>>(exp_e, per_e, ln0g, ln0b, xin, xinh);
    // qkv = x_in @ ipw^T + ipb -> fp16   (288 CTAs, single wave)
    gemm_h128<<<dim3(QKVD / 128, SQ / 128), 256, GEMM_SMEM>>>(xinh, wq, ipb, qkvh, QKVD, DIM);
    // sparse attention (fp16 math) -> fp16 att
    attn_kernel<<<SQ, 192>>>();
    // prj = att @ opw^T + opb   (384 CTAs)
    gemm_h64<false, false><<<dim3(DIM / 64, SQ / 64), 128, GEMM_SMEM64>>>(
        atth, wo, opb, prj, nullptr, DIM, DIM);
    // x1 = LN1(prj + xin), fp32 + fp16
    add_ln_kernel<<<SQ, 256>>>(prj, xin, ln1g, ln1b, x1, x1h);
    // hh = relu(x1 @ w1^T + b1) -> fp16   (192 CTAs)
    gemm_h64<true, true><<<dim3(FFD / 64, SQ / 64), 128, GEMM_SMEM64>>>(
        x1h, wr1, b1, nullptr, hhh, FFD, DIM);
    // ff = hh @ w2^T + b2   (384 CTAs)
    gemm_h64<false, false><<<dim3(DIM / 64, SQ / 64), 128, GEMM_SMEM64>>>(
        hhh, wr2, b2, ff, nullptr, DIM, FFD);
    // out = LN2(x1 + ff), full fp32
    add_ln_kernel<<<SQ, 256>>>(x1, ff, ln2g, ln2b, out, nullptr);
}

// round 14
// speedup vs baseline: 1.0134x; 1.0134x over previous
#include <cuda_runtime.h>
#include <cuda_fp16.h>
#include <cstdint>
#include <math.h>

#define SQ   2048
#define DIM  768
#define NH   12
#define HD   64
#define QKVD 2304
#define FFD  384
#define MAXN 128

// ---------------- scratch (device globals; no allocation allowed) ----------------
__device__ float g_xin[SQ * DIM];     // LN0 output fp32 (for residual)
__device__ float g_prj[SQ * DIM];
__device__ float g_x1 [SQ * DIM];     // LN1 output fp32 (for residual)
__device__ float g_ff [SQ * DIM];
__device__ __half g_qkv_h[SQ * QKVD]; // qkv in fp16 (only attn reads it)
__device__ __half g_xin_h[SQ * DIM];  // fp16 GEMM operands
__device__ __half g_att_h[SQ * DIM];
__device__ __half g_x1_h [SQ * DIM];
__device__ __half g_hh_h [SQ * FFD];
__device__ __half g_wq [QKVD * DIM];
__device__ __half g_wo [DIM * DIM];
__device__ __half g_w1 [FFD * DIM];
__device__ __half g_w2 [DIM * FFD];
__device__ int   g_nbr[SQ * MAXN];
__device__ int   g_cnt[SQ];

// ---------------- PTX helpers (sm_80-era only) ----------------
__device__ __forceinline__ uint32_t smem_u32(const void* p) {
    uint32_t a;
    asm("{ .reg .u64 t; cvta.to.shared.u64 t, %1; cvt.u32.u64 %0, t; }" : "=r"(a) : "l"(p));
    return a;
}
#define CP_ASYNC16(dst, src) \
    asm volatile("cp.async.cg.shared.global [%0], [%1], 16;" :: "r"(dst), "l"(src))
#define CP_COMMIT() asm volatile("cp.async.commit_group;" ::: "memory")
#define CP_WAIT(n)  asm volatile("cp.async.wait_group %0;" :: "n"(n) : "memory")

__device__ __forceinline__ void ldsm_x4(uint32_t (&r)[4], uint32_t addr) {
    asm volatile("ldmatrix.sync.aligned.m8n8.x4.shared.b16 {%0,%1,%2,%3}, [%4];"
                 : "=r"(r[0]), "=r"(r[1]), "=r"(r[2]), "=r"(r[3]) : "r"(addr));
}
__device__ __forceinline__ void ldsm_x2(uint32_t (&r)[2], uint32_t addr) {
    asm volatile("ldmatrix.sync.aligned.m8n8.x2.shared.b16 {%0,%1}, [%2];"
                 : "=r"(r[0]), "=r"(r[1]) : "r"(addr));
}
__device__ __forceinline__ void mma_f16(float (&d)[4], const uint32_t (&a)[4],
                                        const uint32_t (&b)[2]) {
    asm volatile("mma.sync.aligned.m16n8k16.row.col.f32.f16.f16.f32 "
                 "{%0,%1,%2,%3}, {%4,%5,%6,%7}, {%8,%9}, {%0,%1,%2,%3};"
                 : "+f"(d[0]), "+f"(d[1]), "+f"(d[2]), "+f"(d[3])
                 : "r"(a[0]), "r"(a[1]), "r"(a[2]), "r"(a[3]), "r"(b[0]), "r"(b[1]));
}

// fp16 4-term dot: k (2x half2) . q (2x half2) -> float
__device__ __forceinline__ float dot4h(uint2 k, __half2 qa, __half2 qb) {
    __half2 d = __hmul2(*(const __half2*)&k.x, qa);
    d = __hfma2(*(const __half2*)&k.y, qb, d);
    float2 f = __half22float2(d);
    return f.x + f.y;
}

// ---------------- block reduce ----------------
__device__ __forceinline__ float block_sum(float v, float* sh) {
    #pragma unroll
    for (int o = 16; o > 0; o >>= 1) v += __shfl_down_sync(0xffffffffu, v, o);
    if ((threadIdx.x & 31) == 0) sh[threadIdx.x >> 5] = v;
    __syncthreads();
    if (threadIdx.x < 32) {
        float t = (threadIdx.x < 8) ? sh[threadIdx.x] : 0.f;
        #pragma unroll
        for (int o = 4; o > 0; o >>= 1) t += __shfl_down_sync(0xffffffffu, t, o);
        if (threadIdx.x == 0) sh[0] = t;
    }
    __syncthreads();
    float r = sh[0];
    __syncthreads();
    return r;
}

// ---------------- fused (a+b) -> LayerNorm (+ optional fp16 copy) ----------------
__global__ void add_ln_kernel(const float* __restrict__ a, const float* __restrict__ b,
                              const float* __restrict__ g, const float* __restrict__ be,
                              float* __restrict__ out, __half* __restrict__ outh) {
    __shared__ float sh[8];
    int row = blockIdx.x;
    const float* pa = a + (size_t)row * DIM;
    const float* pb = b + (size_t)row * DIM;
    float v[3]; float s = 0.f;
    #pragma unroll
    for (int i = 0; i < 3; i++) { int c = threadIdx.x + i * 256; v[i] = pa[c] + pb[c]; s += v[i]; }
    float mu = block_sum(s, sh) * (1.f / DIM);
    float s2 = 0.f;
    #pragma unroll
    for (int i = 0; i < 3; i++) { float d = v[i] - mu; s2 += d * d; }
    float var = block_sum(s2, sh) * (1.f / DIM);
    float rstd = rsqrtf(var + 1e-5f);
    #pragma unroll
    for (int i = 0; i < 3; i++) {
        int c = threadIdx.x + i * 256;
        float y = (v[i] - mu) * rstd * g[c] + be[c];
        out[(size_t)row * DIM + c] = y;
        if (outh) outh[(size_t)row * DIM + c] = __float2half_rn(y);
    }
}

// ---------------- prep: weight fp16 convert (y<4) + neighbor lists (y==4) --------
__global__ void prep_kernel(const int* __restrict__ adj,
                            const float* __restrict__ s0, __half* d0, int n0,
                            const float* __restrict__ s1, __half* d1, int n1,
                            const float* __restrict__ s2, __half* d2, int n2,
                            const float* __restrict__ s3, __half* d3, int n3) {
    if (blockIdx.y == 4) {
        int q = blockIdx.x;
        __shared__ int cnt;
        if (threadIdx.x == 0) cnt = 0;
        __syncthreads();
        const int4* row = (const int4*)(adj + (size_t)q * SQ);
        for (int c = threadIdx.x; c < SQ / 4; c += blockDim.x) {
            int4 v = row[c];
            int base = c * 4;
            if (v.x) { int p = atomicAdd(&cnt, 1); if (p < MAXN) g_nbr[q * MAXN + p] = base; }
            if (v.y) { int p = atomicAdd(&cnt, 1); if (p < MAXN) g_nbr[q * MAXN + p] = base + 1; }
            if (v.z) { int p = atomicAdd(&cnt, 1); if (p < MAXN) g_nbr[q * MAXN + p] = base + 2; }
            if (v.w) { int p = atomicAdd(&cnt, 1); if (p < MAXN) g_nbr[q * MAXN + p] = base + 3; }
        }
        __syncthreads();
        if (threadIdx.x == 0) g_cnt[q] = cnt < MAXN ? cnt : MAXN;
        return;
    }
    const float* x; __half* d; int n4;
    switch (blockIdx.y) {
        case 0: x = s0; d = d0; n4 = n0; break;
        case 1: x = s1; d = d1; n4 = n1; break;
        case 2: x = s2; d = d2; n4 = n2; break;
        default: x = s3; d = d3; n4 = n3; break;
    }
    int i = blockIdx.x * 256 + threadIdx.x;
    if (i < n4) {
        float4 v = ((const float4*)x)[i];
        __half2* p = (__half2*)(d + (size_t)i * 4);
        p[0] = __half2(__float2half_rn(v.x), __float2half_rn(v.y));
        p[1] = __half2(__float2half_rn(v.z), __float2half_rn(v.w));
    }
}

// ---------------- sparse attention: fp16 math, precomputed offsets ----------------
__global__ void attn_kernel() {
    int q    = blockIdx.x;
    int tid  = threadIdx.x;          // 192 threads
    int head = tid >> 4;             // 0..11
    int l    = tid & 15;             // 0..15 (4 dims each)
    __shared__ __half2 qv2[DIM / 2];
    __shared__ float sc[NH][MAXN];
    __shared__ int   noff[MAXN];     // precomputed element offsets (nbr * QKVD)

    int n = g_cnt[q];
    {
        const __half2* qrow = (const __half2*)(g_qkv_h + (size_t)q * QKVD);
        for (int i = tid; i < DIM / 2; i += 192) qv2[i] = qrow[i];
        for (int i = tid; i < n; i += 192) noff[i] = g_nbr[q * MAXN + i] * QKVD;
    }
    __syncthreads();

    const __half2 qa = qv2[(head * HD + l * 4) >> 1];
    const __half2 qb = qv2[(head * HD + l * 4) >> 1 | 1];
    const int koff = DIM + head * HD + l * 4;

    // score phase: 4 independent dot+reduce chains per round
    int j = 0;
    for (; j + 3 < n; j += 4) {
        const uint2 k0 = *(const uint2*)(g_qkv_h + (size_t)(noff[j]     + koff));
        const uint2 k1 = *(const uint2*)(g_qkv_h + (size_t)(noff[j + 1] + koff));
        const uint2 k2 = *(const uint2*)(g_qkv_h + (size_t)(noff[j + 2] + koff));
        const uint2 k3 = *(const uint2*)(g_qkv_h + (size_t)(noff[j + 3] + koff));
        float s0 = dot4h(k0, qa, qb);
        float s1 = dot4h(k1, qa, qb);
        float s2 = dot4h(k2, qa, qb);
        float s3 = dot4h(k3, qa, qb);
        #pragma unroll
        for (int o = 8; o > 0; o >>= 1) {
            s0 += __shfl_down_sync(0xffffffffu, s0, o, 16);
            s1 += __shfl_down_sync(0xffffffffu, s1, o, 16);
            s2 += __shfl_down_sync(0xffffffffu, s2, o, 16);
            s3 += __shfl_down_sync(0xffffffffu, s3, o, 16);
        }
        if (l == 0) {
            sc[head][j]     = s0 * 0.125f;
            sc[head][j + 1] = s1 * 0.125f;
            sc[head][j + 2] = s2 * 0.125f;
            sc[head][j + 3] = s3 * 0.125f;
        }
    }
    for (; j < n; j++) {
        const uint2 k0 = *(const uint2*)(g_qkv_h + (size_t)(noff[j] + koff));
        float s0 = dot4h(k0, qa, qb);
        #pragma unroll
        for (int o = 8; o > 0; o >>= 1) s0 += __shfl_down_sync(0xffffffffu, s0, o, 16);
        if (l == 0) sc[head][j] = s0 * 0.125f;
    }
    __syncwarp();

    // softmax over neighbors (per head, 16 lanes)
    float m = -INFINITY;
    for (int i = l; i < n; i += 16) m = fmaxf(m, sc[head][i]);
    #pragma unroll
    for (int o = 8; o > 0; o >>= 1) m = fmaxf(m, __shfl_xor_sync(0xffffffffu, m, o, 16));
    float sum = 0.f;
    for (int i = l; i < n; i += 16) { float e = __expf(sc[head][i] - m); sc[head][i] = e; sum += e; }
    #pragma unroll
    for (int o = 8; o > 0; o >>= 1) sum += __shfl_xor_sync(0xffffffffu, sum, o, 16);
    float inv = 1.f / sum;
    __syncwarp();

    // V accumulation, fp32, unroll 4
    const int voff = 2 * DIM + head * HD + l * 4;
    float4 A0 = make_float4(0.f, 0.f, 0.f, 0.f);
    float4 A1 = make_float4(0.f, 0.f, 0.f, 0.f);
    float4 A2 = make_float4(0.f, 0.f, 0.f, 0.f);
    float4 A3 = make_float4(0.f, 0.f, 0.f, 0.f);
    j = 0;
    for (; j + 3 < n; j += 4) {
        float p0 = sc[head][j] * inv,     p1 = sc[head][j + 1] * inv;
        float p2 = sc[head][j + 2] * inv, p3 = sc[head][j + 3] * inv;
        const uint2 v0 = *(const uint2*)(g_qkv_h + (size_t)(noff[j]     + voff));
        const uint2 v1 = *(const uint2*)(g_qkv_h + (size_t)(noff[j + 1] + voff));
        const uint2 v2 = *(const uint2*)(g_qkv_h + (size_t)(noff[j + 2] + voff));
        const uint2 v3 = *(const uint2*)(g_qkv_h + (size_t)(noff[j + 3] + voff));
        float2 a0 = __half22float2(*(const __half2*)&v0.x), a1 = __half22float2(*(const __half2*)&v0.y);
        float2 b0 = __half22float2(*(const __half2*)&v1.x), b1 = __half22float2(*(const __half2*)&v1.y);
        float2 c0 = __half22float2(*(const __half2*)&v2.x), c1 = __half22float2(*(const __half2*)&v2.y);
        float2 e0 = __half22float2(*(const __half2*)&v3.x), e1 = __half22float2(*(const __half2*)&v3.y);
        A0.x += p0 * a0.x; A0.y += p0 * a0.y; A0.z += p0 * a1.x; A0.w += p0 * a1.y;
        A1.x += p1 * b0.x; A1.y += p1 * b0.y; A1.z += p1 * b1.x; A1.w += p1 * b1.y;
        A2.x += p2 * c0.x; A2.y += p2 * c0.y; A2.z += p2 * c1.x; A2.w += p2 * c1.y;
        A3.x += p3 * e0.x; A3.y += p3 * e0.y; A3.z += p3 * e1.x; A3.w += p3 * e1.y;
    }
    for (; j < n; j++) {
        float p0 = sc[head][j] * inv;
        const uint2 v0 = *(const uint2*)(g_qkv_h + (size_t)(noff[j] + voff));
        float2 a0 = __half22float2(*(const __half2*)&v0.x), a1 = __half22float2(*(const __half2*)&v0.y);
        A0.x += p0 * a0.x; A0.y += p0 * a0.y; A0.z += p0 * a1.x; A0.w += p0 * a1.y;
    }
    float rx = A0.x + A1.x + A2.x + A3.x;
    float ry = A0.y + A1.y + A2.y + A3.y;
    float rz = A0.z + A1.z + A2.z + A3.z;
    float rw = A0.w + A1.w + A2.w + A3.w;

    __half2* ph = (__half2*)(g_att_h + (size_t)q * DIM + head * HD + l * 4);
    ph[0] = __half2(__float2half_rn(rx), __float2half_rn(ry));
    ph[1] = __half2(__float2half_rn(rz), __float2half_rn(rw));
}

// ---------------- fp16 GEMM 128x128, 256 threads (2x4 warps of 64x32) -----------
#define RSB      80
#define MATB     (128 * RSB)              // 10240
#define STAGEB   (2 * MATB)               // 20480 (A + B)
#define NSTAGE   3
#define GEMM_SMEM (NSTAGE * STAGEB)       // 61440 -> 2 CTAs/SM

__global__ void __launch_bounds__(256, 2)
gemm_h128(const __half* __restrict__ A, const __half* __restrict__ B,
          const float* __restrict__ bias, __half* __restrict__ Ch, int N, int K) {
    extern __shared__ char dsm[];
    const uint32_t sb = smem_u32(dsm);

    const int tid = threadIdx.x, wid = tid >> 5, lane = tid & 31;
    const int bm = blockIdx.y, bn = blockIdx.x;
    const int m0 = (wid >> 2) * 64, n0 = (wid & 3) * 32;

    const __half* Ag0 = A + (size_t)(bm * 128) * K;
    const __half* Bg0 = B + (size_t)(bn * 128) * K;

    const int lr = tid >> 2, lc = tid & 3;

    float acc[4][4][4];
    #pragma unroll
    for (int i = 0; i < 4; i++)
        #pragma unroll
        for (int j = 0; j < 4; j++)
            #pragma unroll
            for (int v = 0; v < 4; v++) acc[i][j][v] = 0.f;

    const int KT = K >> 5;

    auto load_stage = [&](int s, int kt) {
        uint32_t base = sb + s * STAGEB;
        const __half* Ag = Ag0 + kt * 32;
        const __half* Bg = Bg0 + kt * 32;
        #pragma unroll
        for (int j = 0; j < 2; j++) {
            int r = lr + j * 64;
            CP_ASYNC16(base +        r * RSB + lc * 16, Ag + (size_t)r * K + lc * 8);
            CP_ASYNC16(base + MATB + r * RSB + lc * 16, Bg + (size_t)r * K + lc * 8);
        }
        CP_COMMIT();
    };

    load_stage(0, 0);
    if (KT > 1) load_stage(1, 1); else CP_COMMIT();

    const int arow = lane & 15, ahalf = lane >> 4;
    const int brow = lane & 7,  bhalf = (lane >> 3) & 1;

    int stage = 0;
    for (int kt = 0; kt < KT; kt++) {
        CP_WAIT(1);
        __syncthreads();
        if (kt + 2 < KT) {
            int s = stage + 2; if (s >= NSTAGE) s -= NSTAGE;
            load_stage(s, kt + 2);
        } else CP_COMMIT();

        uint32_t base = sb + stage * STAGEB;
        #pragma unroll
        for (int ks = 0; ks < 2; ks++) {
            uint32_t af[4][4], bf[4][2];
            #pragma unroll
            for (int im = 0; im < 4; im++)
                ldsm_x4(af[im], base + (m0 + im * 16 + arow) * RSB + ks * 32 + ahalf * 16);
            #pragma unroll
            for (int in = 0; in < 4; in++)
                ldsm_x2(bf[in], base + MATB + (n0 + in * 8 + brow) * RSB + ks * 32 + bhalf * 16);
            #pragma unroll
            for (int im = 0; im < 4; im++)
                #pragma unroll
                for (int in = 0; in < 4; in++)
                    mma_f16(acc[im][in], af[im], bf[in]);
        }
        if (++stage == NSTAGE) stage = 0;
    }

    const int crow = lane >> 2, ccol = (lane & 3) * 2;
    #pragma unroll
    for (int im = 0; im < 4; im++) {
        #pragma unroll
        for (int in = 0; in < 4; in++) {
            int col = bn * 128 + n0 + in * 8 + ccol;
            float b0 = bias[col], b1 = bias[col + 1];
            #pragma unroll
            for (int half = 0; half < 2; half++) {
                int row = bm * 128 + m0 + im * 16 + crow + half * 8;
                float v0 = acc[im][in][half * 2 + 0] + b0;
                float v1 = acc[im][in][half * 2 + 1] + b1;
                *(__half2*)(Ch + (size_t)row * N + col) =
                    __half2(__float2half_rn(v0), __float2half_rn(v1));
            }
        }
    }
}

// ---------------- 64x64 fp16 variant (128 threads, 2x2 warps of 32x32) ----------
#define MATB64    (64 * RSB)              // 5120
#define STAGEB64  (2 * MATB64)            // 10240
#define GEMM_SMEM64 (NSTAGE * STAGEB64)   // 30720 -> 4 CTAs/SM

template <bool RELU, bool HOUT>
__global__ void __launch_bounds__(128, 4)
gemm_h64(const __half* __restrict__ A, const __half* __restrict__ B,
         const float* __restrict__ bias, float* __restrict__ C, __half* __restrict__ Ch,
         int N, int K) {
    extern __shared__ char dsm[];
    const uint32_t sb = smem_u32(dsm);

    const int tid = threadIdx.x, wid = tid >> 5, lane = tid & 31;
    const int bm = blockIdx.y, bn = blockIdx.x;
    const int m0 = (wid >> 1) * 32, n0 = (wid & 1) * 32;

    const __half* Ag0 = A + (size_t)(bm * 64) * K;
    const __half* Bg0 = B + (size_t)(bn * 64) * K;

    const int lr = tid >> 2, lc = tid & 3;

    float acc[2][4][4];
    #pragma unroll
    for (int i = 0; i < 2; i++)
        #pragma unroll
        for (int j = 0; j < 4; j++)
            #pragma unroll
            for (int v = 0; v < 4; v++) acc[i][j][v] = 0.f;

    const int KT = K >> 5;

    auto load_stage = [&](int s, int kt) {
        uint32_t base = sb + s * STAGEB64;
        const __half* Ag = Ag0 + kt * 32;
        const __half* Bg = Bg0 + kt * 32;
        #pragma unroll
        for (int j = 0; j < 2; j++) {
            int r = lr + j * 32;
            CP_ASYNC16(base +          r * RSB + lc * 16, Ag + (size_t)r * K + lc * 8);
            CP_ASYNC16(base + MATB64 + r * RSB + lc * 16, Bg + (size_t)r * K + lc * 8);
        }
        CP_COMMIT();
    };

    load_stage(0, 0);
    if (KT > 1) load_stage(1, 1); else CP_COMMIT();

    const int arow = lane & 15, ahalf = lane >> 4;
    const int brow = lane & 7,  bhalf = (lane >> 3) & 1;

    int stage = 0;
    for (int kt = 0; kt < KT; kt++) {
        CP_WAIT(1);
        __syncthreads();
        if (kt + 2 < KT) {
            int s = stage + 2; if (s >= NSTAGE) s -= NSTAGE;
            load_stage(s, kt + 2);
        } else CP_COMMIT();

        uint32_t base = sb + stage * STAGEB64;
        #pragma unroll
        for (int ks = 0; ks < 2; ks++) {
            uint32_t af[2][4], bf[4][2];
            #pragma unroll
            for (int im = 0; im < 2; im++)
                ldsm_x4(af[im], base + (m0 + im * 16 + arow) * RSB + ks * 32 + ahalf * 16);
            #pragma unroll
            for (int in = 0; in < 4; in++)
                ldsm_x2(bf[in], base + MATB64 + (n0 + in * 8 + brow) * RSB + ks * 32 + bhalf * 16);
            #pragma unroll
            for (int im = 0; im < 2; im++)
                #pragma unroll
                for (int in = 0; in < 4; in++)
                    mma_f16(acc[im][in], af[im], bf[in]);
        }
        if (++stage == NSTAGE) stage = 0;
    }

    const int crow = lane >> 2, ccol = (lane & 3) * 2;
    #pragma unroll
    for (int im = 0; im < 2; im++) {
        #pragma unroll
        for (int in = 0; in < 4; in++) {
            int col = bn * 64 + n0 + in * 8 + ccol;
            float b0 = bias[col], b1 = bias[col + 1];
            #pragma unroll
            for (int half = 0; half < 2; half++) {
                int row = bm * 64 + m0 + im * 16 + crow + half * 8;
                float v0 = acc[im][in][half * 2 + 0] + b0;
                float v1 = acc[im][in][half * 2 + 1] + b1;
                if (RELU) { v0 = fmaxf(v0, 0.f); v1 = fmaxf(v1, 0.f); }
                if (HOUT) {
                    *(__half2*)(Ch + (size_t)row * N + col) =
                        __half2(__float2half_rn(v0), __float2half_rn(v1));
                } else {
                    *(float2*)(C + (size_t)row * N + col) = make_float2(v0, v1);
                }
            }
        }
    }
}

// ---------------- launch ----------------
extern "C" void kernel_launch(void* const* d_in, const int* in_sizes, int n_in,
                              void* d_out, int out_size) {
    const float* exp_e = (const float*)d_in[0];
    const float* per_e = (const float*)d_in[1];
    const float* ipw   = (const float*)d_in[2];
    const float* ipb   = (const float*)d_in[3];
    const float* opw   = (const float*)d_in[4];
    const float* opb   = (const float*)d_in[5];
    const float* ln0g  = (const float*)d_in[6];
    const float* ln0b  = (const float*)d_in[7];
    const float* ln1g  = (const float*)d_in[8];
    const float* ln1b  = (const float*)d_in[9];
    const float* ln2g  = (const float*)d_in[10];
    const float* ln2b  = (const float*)d_in[11];
    const float* w1    = (const float*)d_in[12];
    const float* b1    = (const float*)d_in[13];
    const float* w2    = (const float*)d_in[14];
    const float* b2    = (const float*)d_in[15];
    const int*   adj   = (const int*)d_in[16];
    float* out = (float*)d_out;

    float *xin, *prj, *x1, *ff;
    __half *qkvh, *xinh, *atth, *x1h, *hhh, *wq, *wo, *wr1, *wr2;
    cudaGetSymbolAddress((void**)&xin, g_xin);
    cudaGetSymbolAddress((void**)&prj, g_prj);
    cudaGetSymbolAddress((void**)&x1,  g_x1);
    cudaGetSymbolAddress((void**)&ff,  g_ff);
    cudaGetSymbolAddress((void**)&qkvh, g_qkv_h);
    cudaGetSymbolAddress((void**)&xinh, g_xin_h);
    cudaGetSymbolAddress((void**)&atth, g_att_h);
    cudaGetSymbolAddress((void**)&x1h,  g_x1_h);
    cudaGetSymbolAddress((void**)&hhh,  g_hh_h);
    cudaGetSymbolAddress((void**)&wq,  g_wq);
    cudaGetSymbolAddress((void**)&wo,  g_wo);
    cudaGetSymbolAddress((void**)&wr1, g_w1);
    cudaGetSymbolAddress((void**)&wr2, g_w2);

    cudaFuncSetAttribute(gemm_h128, cudaFuncAttributeMaxDynamicSharedMemorySize, GEMM_SMEM);
    cudaFuncSetAttribute(gemm_h64<false, false>, cudaFuncAttributeMaxDynamicSharedMemorySize, GEMM_SMEM64);
    cudaFuncSetAttribute(gemm_h64<true,  true >, cudaFuncAttributeMaxDynamicSharedMemorySize, GEMM_SMEM64);

    // weights -> fp16 + neighbor lists, one launch
    prep_kernel<<<dim3(SQ, 5), 256>>>(adj,
        ipw, wq,  QKVD * DIM / 4,
        opw, wo,  DIM * DIM / 4,
        w1,  wr1, FFD * DIM / 4,
        w2,  wr2, DIM * FFD / 4);
    // x_in = LN0(exp + pert), fp32 + fp16
    add_ln_kernel<<<SQ, 256>>>(exp_e, per_e, ln0g, ln0b, xin, xinh);
    // qkv = x_in @ ipw^T + ipb -> fp16   (288 CTAs, single wave)
    gemm_h128<<<dim3(QKVD / 128, SQ / 128), 256, GEMM_SMEM>>>(xinh, wq, ipb, qkvh, QKVD, DIM);
    // sparse attention (fp16 math) -> fp16 att
    attn_kernel<<<SQ, 192>>>();
    // prj = att @ opw^T + opb   (384 CTAs)
    gemm_h64<false, false><<<dim3(DIM / 64, SQ / 64), 128, GEMM_SMEM64>>>(
        atth, wo, opb, prj, nullptr, DIM, DIM);
    // x1 = LN1(prj + xin), fp32 + fp16
    add_ln_kernel<<<SQ, 256>>>(prj, xin, ln1g, ln1b, x1, x1h);
    // hh = relu(x1 @ w1^T + b1) -> fp16   (192 CTAs)
    gemm_h64<true, true><<<dim3(FFD / 64, SQ / 64), 128, GEMM_SMEM64>>>(
        x1h, wr1, b1, nullptr, hhh, FFD, DIM);
    // ff = hh @ w2^T + b2   (384 CTAs)
    gemm_h64<false, false><<<dim3(DIM / 64, SQ / 64), 128, GEMM_SMEM64>>>(
        hhh, wr2, b2, ff, nullptr, DIM, FFD);
    // out = LN2(x1 + ff), full fp32
    add_ln_kernel<<<SQ, 256>>>(x1, ff, ln2g, ln2b, out, nullptr);
}

// round 16
// speedup vs baseline: 1.0532x; 1.0393x over previous
#include <cuda_runtime.h>
#include <cuda_fp16.h>
#include <cstdint>
#include <math.h>

#define SQ   2048
#define DIM  768
#define NH   12
#define HD   64
#define QKVD 2304
#define FFD  384
#define MAXN 128

// ---------------- scratch (device globals; no allocation allowed) ----------------
__device__ float g_xin[SQ * DIM];     // LN0 output fp32 (for residual)
__device__ float g_prj[SQ * DIM];
__device__ float g_x1 [SQ * DIM];     // LN1 output fp32 (for residual)
__device__ float g_ff [SQ * DIM];
__device__ __half g_qkv_h[SQ * QKVD]; // qkv in fp16 (only attn reads it)
__device__ __half g_xin_h[SQ * DIM];  // fp16 GEMM operands
__device__ __half g_att_h[SQ * DIM];
__device__ __half g_x1_h [SQ * DIM];
__device__ __half g_hh_h [SQ * FFD];
__device__ __half g_wq [QKVD * DIM];
__device__ __half g_wo [DIM * DIM];
__device__ __half g_w1 [FFD * DIM];
__device__ __half g_w2 [DIM * FFD];
__device__ int   g_nbr[SQ * MAXN];
__device__ int   g_cnt[SQ];

// ---------------- PTX helpers (sm_80-era only) ----------------
__device__ __forceinline__ uint32_t smem_u32(const void* p) {
    uint32_t a;
    asm("{ .reg .u64 t; cvta.to.shared.u64 t, %1; cvt.u32.u64 %0, t; }" : "=r"(a) : "l"(p));
    return a;
}
#define CP_ASYNC16(dst, src) \
    asm volatile("cp.async.cg.shared.global [%0], [%1], 16;" :: "r"(dst), "l"(src))
#define CP_COMMIT() asm volatile("cp.async.commit_group;" ::: "memory")
#define CP_WAIT(n)  asm volatile("cp.async.wait_group %0;" :: "n"(n) : "memory")

__device__ __forceinline__ void ldsm_x4(uint32_t (&r)[4], uint32_t addr) {
    asm volatile("ldmatrix.sync.aligned.m8n8.x4.shared.b16 {%0,%1,%2,%3}, [%4];"
                 : "=r"(r[0]), "=r"(r[1]), "=r"(r[2]), "=r"(r[3]) : "r"(addr));
}
__device__ __forceinline__ void ldsm_x2(uint32_t (&r)[2], uint32_t addr) {
    asm volatile("ldmatrix.sync.aligned.m8n8.x2.shared.b16 {%0,%1}, [%2];"
                 : "=r"(r[0]), "=r"(r[1]) : "r"(addr));
}
__device__ __forceinline__ void mma_f16(float (&d)[4], const uint32_t (&a)[4],
                                        const uint32_t (&b)[2]) {
    asm volatile("mma.sync.aligned.m16n8k16.row.col.f32.f16.f16.f32 "
                 "{%0,%1,%2,%3}, {%4,%5,%6,%7}, {%8,%9}, {%0,%1,%2,%3};"
                 : "+f"(d[0]), "+f"(d[1]), "+f"(d[2]), "+f"(d[3])
                 : "r"(a[0]), "r"(a[1]), "r"(a[2]), "r"(a[3]), "r"(b[0]), "r"(b[1]));
}

// fp16 8-term dot: k (4x half2) . q (4x half2) -> float
__device__ __forceinline__ float dot8h(uint4 k, const __half2 (&qh)[4]) {
    __half2 d = __hmul2(*(const __half2*)&k.x, qh[0]);
    d = __hfma2(*(const __half2*)&k.y, qh[1], d);
    d = __hfma2(*(const __half2*)&k.z, qh[2], d);
    d = __hfma2(*(const __half2*)&k.w, qh[3], d);
    float2 f = __half22float2(d);
    return f.x + f.y;
}

// ---------------- block reduce ----------------
__device__ __forceinline__ float block_sum(float v, float* sh) {
    #pragma unroll
    for (int o = 16; o > 0; o >>= 1) v += __shfl_down_sync(0xffffffffu, v, o);
    if ((threadIdx.x & 31) == 0) sh[threadIdx.x >> 5] = v;
    __syncthreads();
    if (threadIdx.x < 32) {
        float t = (threadIdx.x < 8) ? sh[threadIdx.x] : 0.f;
        #pragma unroll
        for (int o = 4; o > 0; o >>= 1) t += __shfl_down_sync(0xffffffffu, t, o);
        if (threadIdx.x == 0) sh[0] = t;
    }
    __syncthreads();
    float r = sh[0];
    __syncthreads();
    return r;
}

// ---------------- fused (a+b) -> LayerNorm (+ optional fp16 copy) ----------------
__global__ void add_ln_kernel(const float* __restrict__ a, const float* __restrict__ b,
                              const float* __restrict__ g, const float* __restrict__ be,
                              float* __restrict__ out, __half* __restrict__ outh) {
    __shared__ float sh[8];
    int row = blockIdx.x;
    const float* pa = a + (size_t)row * DIM;
    const float* pb = b + (size_t)row * DIM;
    float v[3]; float s = 0.f;
    #pragma unroll
    for (int i = 0; i < 3; i++) { int c = threadIdx.x + i * 256; v[i] = pa[c] + pb[c]; s += v[i]; }
    float mu = block_sum(s, sh) * (1.f / DIM);
    float s2 = 0.f;
    #pragma unroll
    for (int i = 0; i < 3; i++) { float d = v[i] - mu; s2 += d * d; }
    float var = block_sum(s2, sh) * (1.f / DIM);
    float rstd = rsqrtf(var + 1e-5f);
    #pragma unroll
    for (int i = 0; i < 3; i++) {
        int c = threadIdx.x + i * 256;
        float y = (v[i] - mu) * rstd * g[c] + be[c];
        out[(size_t)row * DIM + c] = y;
        if (outh) outh[(size_t)row * DIM + c] = __float2half_rn(y);
    }
}

// ---------------- prep: weight fp16 convert (y<4) + neighbor lists (y==4) --------
__global__ void prep_kernel(const int* __restrict__ adj,
                            const float* __restrict__ s0, __half* d0, int n0,
                            const float* __restrict__ s1, __half* d1, int n1,
                            const float* __restrict__ s2, __half* d2, int n2,
                            const float* __restrict__ s3, __half* d3, int n3) {
    if (blockIdx.y == 4) {
        int q = blockIdx.x;
        __shared__ int cnt;
        if (threadIdx.x == 0) cnt = 0;
        __syncthreads();
        const int4* row = (const int4*)(adj + (size_t)q * SQ);
        for (int c = threadIdx.x; c < SQ / 4; c += blockDim.x) {
            int4 v = row[c];
            int base = c * 4;
            if (v.x) { int p = atomicAdd(&cnt, 1); if (p < MAXN) g_nbr[q * MAXN + p] = base; }
            if (v.y) { int p = atomicAdd(&cnt, 1); if (p < MAXN) g_nbr[q * MAXN + p] = base + 1; }
            if (v.z) { int p = atomicAdd(&cnt, 1); if (p < MAXN) g_nbr[q * MAXN + p] = base + 2; }
            if (v.w) { int p = atomicAdd(&cnt, 1); if (p < MAXN) g_nbr[q * MAXN + p] = base + 3; }
        }
        __syncthreads();
        if (threadIdx.x == 0) g_cnt[q] = cnt < MAXN ? cnt : MAXN;
        return;
    }
    const float* x; __half* d; int n4;
    switch (blockIdx.y) {
        case 0: x = s0; d = d0; n4 = n0; break;
        case 1: x = s1; d = d1; n4 = n1; break;
        case 2: x = s2; d = d2; n4 = n2; break;
        default: x = s3; d = d3; n4 = n3; break;
    }
    int i = blockIdx.x * 256 + threadIdx.x;
    if (i < n4) {
        float4 v = ((const float4*)x)[i];
        __half2* p = (__half2*)(d + (size_t)i * 4);
        p[0] = __half2(__float2half_rn(v.x), __float2half_rn(v.y));
        p[1] = __half2(__float2half_rn(v.z), __float2half_rn(v.w));
    }
}

// ---------------- sparse attention: 8-lane score groups (group-local masks) -------
__global__ void attn_kernel() {
    int q    = blockIdx.x;
    int tid  = threadIdx.x;          // 192 threads
    int head = tid >> 4;             // 0..11 (softmax + V phase)
    int l    = tid & 15;             // 0..15
    int l8   = tid & 7;              // score phase: 8-lane groups
    int jp   = (tid >> 3) & 1;       // j parity handled by this group
    // group-local shuffle mask: the 8 lanes of this group only (legal under divergence)
    const unsigned m8 = 0xffu << (((tid & 31) >> 3) << 3);
    __shared__ __half2 qv2[DIM / 2];
    __shared__ float sc[NH][MAXN];
    __shared__ int   noff[MAXN];     // precomputed element offsets (nbr * QKVD)

    int n = g_cnt[q];
    {
        const __half2* qrow = (const __half2*)(g_qkv_h + (size_t)q * QKVD);
        for (int i = tid; i < DIM / 2; i += 192) qv2[i] = qrow[i];
        for (int i = tid; i < n; i += 192) noff[i] = g_nbr[q * MAXN + i] * QKVD;
    }
    __syncthreads();

    // score phase: each 8-lane group computes full 64-dim dots for j = jp, jp+2, ...
    {
        __half2 qh[4];
        int base = (head * HD + l8 * 8) >> 1;
        qh[0] = qv2[base]; qh[1] = qv2[base + 1]; qh[2] = qv2[base + 2]; qh[3] = qv2[base + 3];
        const int koff = DIM + head * HD + l8 * 8;

        int j = jp;
        for (; j + 2 < n; j += 4) {       // this group: neighbors j and j+2
            const uint4 k0 = *(const uint4*)(g_qkv_h + (size_t)(noff[j]     + koff));
            const uint4 k1 = *(const uint4*)(g_qkv_h + (size_t)(noff[j + 2] + koff));
            float s0 = dot8h(k0, qh);
            float s1 = dot8h(k1, qh);
            #pragma unroll
            for (int o = 4; o > 0; o >>= 1) {
                s0 += __shfl_down_sync(m8, s0, o, 8);
                s1 += __shfl_down_sync(m8, s1, o, 8);
            }
            if (l8 == 0) { sc[head][j] = s0 * 0.125f; sc[head][j + 2] = s1 * 0.125f; }
        }
        for (; j < n; j += 2) {
            const uint4 k0 = *(const uint4*)(g_qkv_h + (size_t)(noff[j] + koff));
            float s0 = dot8h(k0, qh);
            #pragma unroll
            for (int o = 4; o > 0; o >>= 1) s0 += __shfl_down_sync(m8, s0, o, 8);
            if (l8 == 0) sc[head][j] = s0 * 0.125f;
        }
    }
    __syncwarp();

    // softmax over neighbors (per head, 16 lanes)
    float m = -INFINITY;
    for (int i = l; i < n; i += 16) m = fmaxf(m, sc[head][i]);
    #pragma unroll
    for (int o = 8; o > 0; o >>= 1) m = fmaxf(m, __shfl_xor_sync(0xffffffffu, m, o, 16));
    float sum = 0.f;
    for (int i = l; i < n; i += 16) { float e = __expf(sc[head][i] - m); sc[head][i] = e; sum += e; }
    #pragma unroll
    for (int o = 8; o > 0; o >>= 1) sum += __shfl_xor_sync(0xffffffffu, sum, o, 16);
    float inv = 1.f / sum;
    __syncwarp();

    // V accumulation, fp32, unroll 4 (dims-parallel, 16 lanes x 4 dims)
    const int voff = 2 * DIM + head * HD + l * 4;
    float4 A0 = make_float4(0.f, 0.f, 0.f, 0.f);
    float4 A1 = make_float4(0.f, 0.f, 0.f, 0.f);
    float4 A2 = make_float4(0.f, 0.f, 0.f, 0.f);
    float4 A3 = make_float4(0.f, 0.f, 0.f, 0.f);
    int j = 0;
    for (; j + 3 < n; j += 4) {
        float p0 = sc[head][j] * inv,     p1 = sc[head][j + 1] * inv;
        float p2 = sc[head][j + 2] * inv, p3 = sc[head][j + 3] * inv;
        const uint2 v0 = *(const uint2*)(g_qkv_h + (size_t)(noff[j]     + voff));
        const uint2 v1 = *(const uint2*)(g_qkv_h + (size_t)(noff[j + 1] + voff));
        const uint2 v2 = *(const uint2*)(g_qkv_h + (size_t)(noff[j + 2] + voff));
        const uint2 v3 = *(const uint2*)(g_qkv_h + (size_t)(noff[j + 3] + voff));
        float2 a0 = __half22float2(*(const __half2*)&v0.x), a1 = __half22float2(*(const __half2*)&v0.y);
        float2 b0 = __half22float2(*(const __half2*)&v1.x), b1 = __half22float2(*(const __half2*)&v1.y);
        float2 c0 = __half22float2(*(const __half2*)&v2.x), c1 = __half22float2(*(const __half2*)&v2.y);
        float2 e0 = __half22float2(*(const __half2*)&v3.x), e1 = __half22float2(*(const __half2*)&v3.y);
        A0.x += p0 * a0.x; A0.y += p0 * a0.y; A0.z += p0 * a1.x; A0.w += p0 * a1.y;
        A1.x += p1 * b0.x; A1.y += p1 * b0.y; A1.z += p1 * b1.x; A1.w += p1 * b1.y;
        A2.x += p2 * c0.x; A2.y += p2 * c0.y; A2.z += p2 * c1.x; A2.w += p2 * c1.y;
        A3.x += p3 * e0.x; A3.y += p3 * e0.y; A3.z += p3 * e1.x; A3.w += p3 * e1.y;
    }
    for (; j < n; j++) {
        float p0 = sc[head][j] * inv;
        const uint2 v0 = *(const uint2*)(g_qkv_h + (size_t)(noff[j] + voff));
        float2 a0 = __half22float2(*(const __half2*)&v0.x), a1 = __half22float2(*(const __half2*)&v0.y);
        A0.x += p0 * a0.x; A0.y += p0 * a0.y; A0.z += p0 * a1.x; A0.w += p0 * a1.y;
    }
    float rx = A0.x + A1.x + A2.x + A3.x;
    float ry = A0.y + A1.y + A2.y + A3.y;
    float rz = A0.z + A1.z + A2.z + A3.z;
    float rw = A0.w + A1.w + A2.w + A3.w;

    __half2* ph = (__half2*)(g_att_h + (size_t)q * DIM + head * HD + l * 4);
    ph[0] = __half2(__float2half_rn(rx), __float2half_rn(ry));
    ph[1] = __half2(__float2half_rn(rz), __float2half_rn(rw));
}

// ---------------- fp16 GEMM 128x128, 256 threads (2x4 warps of 64x32) -----------
#define RSB      80
#define MATB     (128 * RSB)              // 10240
#define STAGEB   (2 * MATB)               // 20480 (A + B)
#define NSTAGE   3
#define GEMM_SMEM (NSTAGE * STAGEB)       // 61440 -> 2 CTAs/SM

__global__ void __launch_bounds__(256, 2)
gemm_h128(const __half* __restrict__ A, const __half* __restrict__ B,
          const float* __restrict__ bias, __half* __restrict__ Ch, int N, int K) {
    extern __shared__ char dsm[];
    const uint32_t sb = smem_u32(dsm);

    const int tid = threadIdx.x, wid = tid >> 5, lane = tid & 31;
    const int bm = blockIdx.y, bn = blockIdx.x;
    const int m0 = (wid >> 2) * 64, n0 = (wid & 3) * 32;

    const __half* Ag0 = A + (size_t)(bm * 128) * K;
    const __half* Bg0 = B + (size_t)(bn * 128) * K;

    const int lr = tid >> 2, lc = tid & 3;

    float acc[4][4][4];
    #pragma unroll
    for (int i = 0; i < 4; i++)
        #pragma unroll
        for (int j = 0; j < 4; j++)
            #pragma unroll
            for (int v = 0; v < 4; v++) acc[i][j][v] = 0.f;

    const int KT = K >> 5;

    auto load_stage = [&](int s, int kt) {
        uint32_t base = sb + s * STAGEB;
        const __half* Ag = Ag0 + kt * 32;
        const __half* Bg = Bg0 + kt * 32;
        #pragma unroll
        for (int j = 0; j < 2; j++) {
            int r = lr + j * 64;
            CP_ASYNC16(base +        r * RSB + lc * 16, Ag + (size_t)r * K + lc * 8);
            CP_ASYNC16(base + MATB + r * RSB + lc * 16, Bg + (size_t)r * K + lc * 8);
        }
        CP_COMMIT();
    };

    load_stage(0, 0);
    if (KT > 1) load_stage(1, 1); else CP_COMMIT();

    const int arow = lane & 15, ahalf = lane >> 4;
    const int brow = lane & 7,  bhalf = (lane >> 3) & 1;

    int stage = 0;
    for (int kt = 0; kt < KT; kt++) {
        CP_WAIT(1);
        __syncthreads();
        if (kt + 2 < KT) {
            int s = stage + 2; if (s >= NSTAGE) s -= NSTAGE;
            load_stage(s, kt + 2);
        } else CP_COMMIT();

        uint32_t base = sb + stage * STAGEB;
        #pragma unroll
        for (int ks = 0; ks < 2; ks++) {
            uint32_t af[4][4], bf[4][2];
            #pragma unroll
            for (int im = 0; im < 4; im++)
                ldsm_x4(af[im], base + (m0 + im * 16 + arow) * RSB + ks * 32 + ahalf * 16);
            #pragma unroll
            for (int in = 0; in < 4; in++)
                ldsm_x2(bf[in], base + MATB + (n0 + in * 8 + brow) * RSB + ks * 32 + bhalf * 16);
            #pragma unroll
            for (int im = 0; im < 4; im++)
                #pragma unroll
                for (int in = 0; in < 4; in++)
                    mma_f16(acc[im][in], af[im], bf[in]);
        }
        if (++stage == NSTAGE) stage = 0;
    }

    const int crow = lane >> 2, ccol = (lane & 3) * 2;
    #pragma unroll
    for (int im = 0; im < 4; im++) {
        #pragma unroll
        for (int in = 0; in < 4; in++) {
            int col = bn * 128 + n0 + in * 8 + ccol;
            float b0 = bias[col], b1 = bias[col + 1];
            #pragma unroll
            for (int half = 0; half < 2; half++) {
                int row = bm * 128 + m0 + im * 16 + crow + half * 8;
                float v0 = acc[im][in][half * 2 + 0] + b0;
                float v1 = acc[im][in][half * 2 + 1] + b1;
                *(__half2*)(Ch + (size_t)row * N + col) =
                    __half2(__float2half_rn(v0), __float2half_rn(v1));
            }
        }
    }
}

// ---------------- 64x64 fp16 variant (128 threads, 2x2 warps of 32x32) ----------
#define MATB64    (64 * RSB)              // 5120
#define STAGEB64  (2 * MATB64)            // 10240
#define GEMM_SMEM64 (NSTAGE * STAGEB64)   // 30720 -> 4 CTAs/SM

template <bool RELU, bool HOUT>
__global__ void __launch_bounds__(128, 4)
gemm_h64(const __half* __restrict__ A, const __half* __restrict__ B,
         const float* __restrict__ bias, float* __restrict__ C, __half* __restrict__ Ch,
         int N, int K) {
    extern __shared__ char dsm[];
    const uint32_t sb = smem_u32(dsm);

    const int tid = threadIdx.x, wid = tid >> 5, lane = tid & 31;
    const int bm = blockIdx.y, bn = blockIdx.x;
    const int m0 = (wid >> 1) * 32, n0 = (wid & 1) * 32;

    const __half* Ag0 = A + (size_t)(bm * 64) * K;
    const __half* Bg0 = B + (size_t)(bn * 64) * K;

    const int lr = tid >> 2, lc = tid & 3;

    float acc[2][4][4];
    #pragma unroll
    for (int i = 0; i < 2; i++)
        #pragma unroll
        for (int j = 0; j < 4; j++)
            #pragma unroll
            for (int v = 0; v < 4; v++) acc[i][j][v] = 0.f;

    const int KT = K >> 5;

    auto load_stage = [&](int s, int kt) {
        uint32_t base = sb + s * STAGEB64;
        const __half* Ag = Ag0 + kt * 32;
        const __half* Bg = Bg0 + kt * 32;
        #pragma unroll
        for (int j = 0; j < 2; j++) {
            int r = lr + j * 32;
            CP_ASYNC16(base +          r * RSB + lc * 16, Ag + (size_t)r * K + lc * 8);
            CP_ASYNC16(base + MATB64 + r * RSB + lc * 16, Bg + (size_t)r * K + lc * 8);
        }
        CP_COMMIT();
    };

    load_stage(0, 0);
    if (KT > 1) load_stage(1, 1); else CP_COMMIT();

    const int arow = lane & 15, ahalf = lane >> 4;
    const int brow = lane & 7,  bhalf = (lane >> 3) & 1;

    int stage = 0;
    for (int kt = 0; kt < KT; kt++) {
        CP_WAIT(1);
        __syncthreads();
        if (kt + 2 < KT) {
            int s = stage + 2; if (s >= NSTAGE) s -= NSTAGE;
            load_stage(s, kt + 2);
        } else CP_COMMIT();

        uint32_t base = sb + stage * STAGEB64;
        #pragma unroll
        for (int ks = 0; ks < 2; ks++) {
            uint32_t af[2][4], bf[4][2];
            #pragma unroll
            for (int im = 0; im < 2; im++)
                ldsm_x4(af[im], base + (m0 + im * 16 + arow) * RSB + ks * 32 + ahalf * 16);
            #pragma unroll
            for (int in = 0; in < 4; in++)
                ldsm_x2(bf[in], base + MATB64 + (n0 + in * 8 + brow) * RSB + ks * 32 + bhalf * 16);
            #pragma unroll
            for (int im = 0; im < 2; im++)
                #pragma unroll
                for (int in = 0; in < 4; in++)
                    mma_f16(acc[im][in], af[im], bf[in]);
        }
        if (++stage == NSTAGE) stage = 0;
    }

    const int crow = lane >> 2, ccol = (lane & 3) * 2;
    #pragma unroll
    for (int im = 0; im < 2; im++) {
        #pragma unroll
        for (int in = 0; in < 4; in++) {
            int col = bn * 64 + n0 + in * 8 + ccol;
            float b0 = bias[col], b1 = bias[col + 1];
            #pragma unroll
            for (int half = 0; half < 2; half++) {
                int row = bm * 64 + m0 + im * 16 + crow + half * 8;
                float v0 = acc[im][in][half * 2 + 0] + b0;
                float v1 = acc[im][in][half * 2 + 1] + b1;
                if (RELU) { v0 = fmaxf(v0, 0.f); v1 = fmaxf(v1, 0.f); }
                if (HOUT) {
                    *(__half2*)(Ch + (size_t)row * N + col) =
                        __half2(__float2half_rn(v0), __float2half_rn(v1));
                } else {
                    *(float2*)(C + (size_t)row * N + col) = make_float2(v0, v1);
                }
            }
        }
    }
}

// ---------------- launch ----------------
extern "C" void kernel_launch(void* const* d_in, const int* in_sizes, int n_in,
                              void* d_out, int out_size) {
    const float* exp_e = (const float*)d_in[0];
    const float* per_e = (const float*)d_in[1];
    const float* ipw   = (const float*)d_in[2];
    const float* ipb   = (const float*)d_in[3];
    const float* opw   = (const float*)d_in[4];
    const float* opb   = (const float*)d_in[5];
    const float* ln0g  = (const float*)d_in[6];
    const float* ln0b  = (const float*)d_in[7];
    const float* ln1g  = (const float*)d_in[8];
    const float* ln1b  = (const float*)d_in[9];
    const float* ln2g  = (const float*)d_in[10];
    const float* ln2b  = (const float*)d_in[11];
    const float* w1    = (const float*)d_in[12];
    const float* b1    = (const float*)d_in[13];
    const float* w2    = (const float*)d_in[14];
    const float* b2    = (const float*)d_in[15];
    const int*   adj   = (const int*)d_in[16];
    float* out = (float*)d_out;

    float *xin, *prj, *x1, *ff;
    __half *qkvh, *xinh, *atth, *x1h, *hhh, *wq, *wo, *wr1, *wr2;
    cudaGetSymbolAddress((void**)&xin, g_xin);
    cudaGetSymbolAddress((void**)&prj, g_prj);
    cudaGetSymbolAddress((void**)&x1,  g_x1);
    cudaGetSymbolAddress((void**)&ff,  g_ff);
    cudaGetSymbolAddress((void**)&qkvh, g_qkv_h);
    cudaGetSymbolAddress((void**)&xinh, g_xin_h);
    cudaGetSymbolAddress((void**)&atth, g_att_h);
    cudaGetSymbolAddress((void**)&x1h,  g_x1_h);
    cudaGetSymbolAddress((void**)&hhh,  g_hh_h);
    cudaGetSymbolAddress((void**)&wq,  g_wq);
    cudaGetSymbolAddress((void**)&wo,  g_wo);
    cudaGetSymbolAddress((void**)&wr1, g_w1);
    cudaGetSymbolAddress((void**)&wr2, g_w2);

    cudaFuncSetAttribute(gemm_h128, cudaFuncAttributeMaxDynamicSharedMemorySize, GEMM_SMEM);
    cudaFuncSetAttribute(gemm_h64<false, false>, cudaFuncAttributeMaxDynamicSharedMemorySize, GEMM_SMEM64);
    cudaFuncSetAttribute(gemm_h64<true,  true >, cudaFuncAttributeMaxDynamicSharedMemorySize, GEMM_SMEM64);

    // weights -> fp16 + neighbor lists, one launch
    prep_kernel<<<dim3(SQ, 5), 256>>>(adj,
        ipw, wq,  QKVD * DIM / 4,
        opw, wo,  DIM * DIM / 4,
        w1,  wr1, FFD * DIM / 4,
        w2,  wr2, DIM * FFD / 4);
    // x_in = LN0(exp + pert), fp32 + fp16
    add_ln_kernel<<<SQ, 256>>>(exp_e, per_e, ln0g, ln0b, xin, xinh);
    // qkv = x_in @ ipw^T + ipb -> fp16   (288 CTAs, single wave)
    gemm_h128<<<dim3(QKVD / 128, SQ / 128), 256, GEMM_SMEM>>>(xinh, wq, ipb, qkvh, QKVD, DIM);
    // sparse attention (fp16 math) -> fp16 att
    attn_kernel<<<SQ, 192>>>();
    // prj = att @ opw^T + opb   (384 CTAs)
    gemm_h64<false, false><<<dim3(DIM / 64, SQ / 64), 128, GEMM_SMEM64>>>(
        atth, wo, opb, prj, nullptr, DIM, DIM);
    // x1 = LN1(prj + xin), fp32 + fp16
    add_ln_kernel<<<SQ, 256>>>(prj, xin, ln1g, ln1b, x1, x1h);
    // hh = relu(x1 @ w1^T + b1) -> fp16   (192 CTAs)
    gemm_h64<true, true><<<dim3(FFD / 64, SQ / 64), 128, GEMM_SMEM64>>>(
        x1h, wr1, b1, nullptr, hhh, FFD, DIM);
    // ff = hh @ w2^T + b2   (384 CTAs)
    gemm_h64<false, false><<<dim3(DIM / 64, SQ / 64), 128, GEMM_SMEM64>>>(
        hhh, wr2, b2, ff, nullptr, DIM, FFD);
    // out = LN2(x1 + ff), full fp32
    add_ln_kernel<<<SQ, 256>>>(x1, ff, ln2g, ln2b, out, nullptr);
}